// round 5
// baseline (speedup 1.0000x reference)
#include <cuda_runtime.h>
#include <cstdint>

#define N_NODES 50000
#define N_EDGES 800000
#define N_GRAPHS 2048
#define IN_DIM 128
#define HID 256
#define BN_EPS 1e-5f

// ---------------- scratch (no allocations allowed) ----------------
__device__ __align__(16) float g_deg[N_NODES];
__device__ __align__(16) float g_dinv[N_NODES];
__device__ __align__(16) float g_self[N_NODES];
__device__ __align__(16) float g_enorm[N_EDGES];
__device__ __align__(16) float g_H[(size_t)N_NODES * HID];   // h = X @ W
__device__ __align__(16) float g_X[(size_t)N_NODES * HID];   // activations
__device__ __align__(16) float g_pool[(size_t)N_GRAPHS * HID];
__device__ __align__(16) float g_cnt[N_GRAPHS];
__device__ __align__(16) float g_sc[HID];
__device__ __align__(16) float g_sh[HID];
__device__ int g_is64;

// ---------------- index dtype sniffing ----------------
// Reference asks for int64 indices, but JAX demotes to int32 unless x64 is
// enabled, so the actual buffer dtype is unknown. For int64 values < 2^31
// every high word is zero; for int32 the odd words are random node ids.
__global__ void k_sniff(const unsigned* __restrict__ ei_raw) {
    unsigned acc = 0;
    for (int i = 1; i < 128; i += 2) acc |= ei_raw[i];
    g_is64 = (acc == 0) ? 1 : 0;
}

__device__ __forceinline__ int idx_at(const void* base, long long i) {
    if (g_is64) return (int)((const long long*)base)[i];
    return ((const int*)base)[i];
}

// ---------------- degree / norms ----------------
__global__ void k_zero_deg() {
    int i = blockIdx.x * blockDim.x + threadIdx.x;
    if (i < N_NODES) g_deg[i] = 0.0f;
}

__global__ void k_deg(const void* __restrict__ ei) {
    int e = blockIdx.x * blockDim.x + threadIdx.x;
    if (e < N_EDGES) {
        int d = idx_at(ei, (long long)N_EDGES + e);
        atomicAdd(&g_deg[d], 1.0f);
    }
}

__global__ void k_norms() {
    int i = blockIdx.x * blockDim.x + threadIdx.x;
    if (i < N_NODES) {
        float d = g_deg[i] + 1.0f;   // self loop
        g_dinv[i] = rsqrtf(d);
        g_self[i] = 1.0f / d;
    }
}

__global__ void k_enorm(const void* __restrict__ ei) {
    int e = blockIdx.x * blockDim.x + threadIdx.x;
    if (e < N_EDGES) {
        int s = idx_at(ei, e);
        int d = idx_at(ei, (long long)N_EDGES + e);
        g_enorm[e] = g_dinv[s] * g_dinv[d];
    }
}

// ---------------- GEMM: g_H = A[N,K] @ W[K,256] ----------------
// BM=64, BN=64, BK=16, 256 threads, 4x4 per thread.
template<int K, bool USE_GX>
__global__ __launch_bounds__(256)
void k_gemm(const float* __restrict__ Ain, const float* __restrict__ W) {
    __shared__ float As[16][68];
    __shared__ float Bs[16][68];

    const float* A = USE_GX ? (const float*)g_X : Ain;
    int t = threadIdx.x;
    int tx = t & 15, ty = t >> 4;
    int rowBase = blockIdx.x * 64;
    int colBase = blockIdx.y * 64;

    float acc[4][4] = {};

    for (int k0 = 0; k0 < K; k0 += 16) {
        // Load A tile (64 rows x 16 k), transposed into As[k][row]
        {
            int r = t >> 2, kq = t & 3;
            int row = rowBase + r;
            float4 v = make_float4(0.f, 0.f, 0.f, 0.f);
            if (row < N_NODES)
                v = *(const float4*)(A + (size_t)row * K + k0 + kq * 4);
            As[kq * 4 + 0][r] = v.x;
            As[kq * 4 + 1][r] = v.y;
            As[kq * 4 + 2][r] = v.z;
            As[kq * 4 + 3][r] = v.w;
        }
        // Load B tile (16 k x 64 cols)
        {
            int kk = t >> 4, cq = t & 15;
            float4 v = *(const float4*)(W + (size_t)(k0 + kk) * HID + colBase + cq * 4);
            *(float4*)&Bs[kk][cq * 4] = v;
        }
        __syncthreads();

        #pragma unroll
        for (int k = 0; k < 16; k++) {
            float4 a = *(const float4*)&As[k][ty * 4];
            float4 b = *(const float4*)&Bs[k][tx * 4];
            float av[4] = {a.x, a.y, a.z, a.w};
            float bv[4] = {b.x, b.y, b.z, b.w};
            #pragma unroll
            for (int i = 0; i < 4; i++)
                #pragma unroll
                for (int j = 0; j < 4; j++)
                    acc[i][j] += av[i] * bv[j];
        }
        __syncthreads();
    }

    #pragma unroll
    for (int i = 0; i < 4; i++) {
        int row = rowBase + ty * 4 + i;
        if (row < N_NODES) {
            float4 v = make_float4(acc[i][0], acc[i][1], acc[i][2], acc[i][3]);
            *(float4*)(g_H + (size_t)row * HID + colBase + tx * 4) = v;
        }
    }
}

// ---------------- aggregation ----------------
// X_new = b + H * self_norm  (before edge scatter)
__global__ void k_init_agg(const float* __restrict__ bias) {
    int tid = blockIdx.x * blockDim.x + threadIdx.x;
    if (tid >= N_NODES * (HID / 4)) return;
    int i = tid >> 6;
    int j = (tid & 63) << 2;
    float s = g_self[i];
    float4 h = *(const float4*)(g_H + (size_t)i * HID + j);
    float4 b = *(const float4*)(bias + j);
    float4 o = make_float4(b.x + h.x * s, b.y + h.y * s,
                           b.z + h.z * s, b.w + h.w * s);
    *(float4*)(g_X + (size_t)i * HID + j) = o;
}

// X_new[dst] += H[src] * enorm[e]
// 64 threads/edge; thread t handles channels {t, t+64, t+128, t+192}
// (atomics 256B apart -> stay scalar; consecutive lanes coalesce).
__global__ void k_scatter(const void* __restrict__ ei) {
    int tid = blockIdx.x * blockDim.x + threadIdx.x;
    int e = tid >> 6;
    if (e >= N_EDGES) return;
    int t = tid & 63;
    int s = idx_at(ei, e);
    int d = idx_at(ei, (long long)N_EDGES + e);
    float w = g_enorm[e];
    const float* hp = g_H + (size_t)s * HID;
    float*       p  = g_X + (size_t)d * HID;
    atomicAdd(p + t,       hp[t]       * w);
    atomicAdd(p + t + 64,  hp[t + 64]  * w);
    atomicAdd(p + t + 128, hp[t + 128] * w);
    atomicAdd(p + t + 192, hp[t + 192] * w);
}

// ---------------- BN + ReLU ----------------
__global__ void k_bnprep(const float* __restrict__ gamma,
                         const float* __restrict__ beta,
                         const float* __restrict__ mean,
                         const float* __restrict__ var) {
    int j = threadIdx.x;   // 256 threads
    float sc = gamma[j] * rsqrtf(var[j] + BN_EPS);
    g_sc[j] = sc;
    g_sh[j] = beta[j] - mean[j] * sc;
}

__global__ void k_bnrelu() {
    int tid = blockIdx.x * blockDim.x + threadIdx.x;
    if (tid >= N_NODES * (HID / 4)) return;
    int j = (tid & 63) << 2;
    float4 x = *(const float4*)(g_X + (size_t)tid * 4);
    float4 sc = *(const float4*)(g_sc + j);
    float4 sh = *(const float4*)(g_sh + j);
    x.x = fmaxf(x.x * sc.x + sh.x, 0.f);
    x.y = fmaxf(x.y * sc.y + sh.y, 0.f);
    x.z = fmaxf(x.z * sc.z + sh.z, 0.f);
    x.w = fmaxf(x.w * sc.w + sh.w, 0.f);
    *(float4*)(g_X + (size_t)tid * 4) = x;
}

// ---------------- pooling ----------------
__global__ void k_zero_pool() {
    int tid = blockIdx.x * blockDim.x + threadIdx.x;
    if (tid < N_GRAPHS * HID) g_pool[tid] = 0.f;
    if (tid < N_GRAPHS) g_cnt[tid] = 0.f;
}

// Same strided-channel layout as k_scatter.
__global__ void k_pool(const void* __restrict__ batch) {
    int tid = blockIdx.x * blockDim.x + threadIdx.x;
    int i = tid >> 6;
    if (i >= N_NODES) return;
    int t = tid & 63;
    int g = idx_at(batch, i);
    const float* xp = g_X + (size_t)i * HID;
    float*       p  = g_pool + (size_t)g * HID;
    atomicAdd(p + t,       xp[t]);
    atomicAdd(p + t + 64,  xp[t + 64]);
    atomicAdd(p + t + 128, xp[t + 128]);
    atomicAdd(p + t + 192, xp[t + 192]);
    if (t == 0) atomicAdd(&g_cnt[g], 1.0f);
}

// ---------------- MLP head: one block per graph ----------------
__global__ __launch_bounds__(128)
void k_mlp(const float* __restrict__ lin1W, const float* __restrict__ lin1b,
           const float* __restrict__ lin2W, const float* __restrict__ lin2b,
           float* __restrict__ out) {
    __shared__ float row[HID];
    __shared__ float red4[4];
    int g = blockIdx.x;
    int t = threadIdx.x;   // 128

    float c = fmaxf(g_cnt[g], 1.0f);
    float inv = 1.0f / c;
    row[t]       = g_pool[(size_t)g * HID + t] * inv;
    row[t + 128] = g_pool[(size_t)g * HID + t + 128] * inv;
    __syncthreads();

    float acc = lin1b[t];
    #pragma unroll 8
    for (int k = 0; k < HID; k++)
        acc += row[k] * lin1W[(size_t)k * 128 + t];
    float h = fmaxf(acc, 0.f);

    float p = h * lin2W[t];
    #pragma unroll
    for (int o = 16; o > 0; o >>= 1)
        p += __shfl_down_sync(0xffffffffu, p, o);
    if ((t & 31) == 0) red4[t >> 5] = p;
    __syncthreads();
    if (t == 0) out[g] = red4[0] + red4[1] + red4[2] + red4[3] + lin2b[0];
}

// ---------------- launch ----------------
extern "C" void kernel_launch(void* const* d_in, const int* in_sizes, int n_in,
                              void* d_out, int out_size) {
    const float* x      = (const float*)d_in[0];
    const void*  ei     = d_in[1];
    const void*  batch  = d_in[2];
    const float* convW0 = (const float*)d_in[3];
    const float* convWs = (const float*)d_in[4];
    const float* convB  = (const float*)d_in[5];
    const float* bn_g   = (const float*)d_in[6];
    const float* bn_b   = (const float*)d_in[7];
    const float* bn_m   = (const float*)d_in[8];
    const float* bn_v   = (const float*)d_in[9];
    const float* lin1W  = (const float*)d_in[10];
    const float* lin1b  = (const float*)d_in[11];
    const float* lin2W  = (const float*)d_in[12];
    const float* lin2b  = (const float*)d_in[13];
    float* out = (float*)d_out;

    const int TPB = 256;
    int nodeBlocks = (N_NODES + TPB - 1) / TPB;
    int edgeBlocks = (N_EDGES + TPB - 1) / TPB;
    int elemBlocks = (N_NODES * (HID / 4) + TPB - 1) / TPB;      // 12500
    int scatBlocks = (int)(((long long)N_EDGES * 64 + TPB - 1) / TPB); // 200000
    int poolBlocks = (N_NODES * 64 + TPB - 1) / TPB;             // 12500

    k_sniff<<<1, 1>>>((const unsigned*)ei);
    k_zero_deg<<<nodeBlocks, TPB>>>();
    k_deg<<<edgeBlocks, TPB>>>(ei);
    k_norms<<<nodeBlocks, TPB>>>();
    k_enorm<<<edgeBlocks, TPB>>>(ei);

    dim3 ggrid((N_NODES + 63) / 64, HID / 64);

    for (int l = 0; l < 4; l++) {
        if (l == 0) {
            k_gemm<IN_DIM, false><<<ggrid, 256>>>(x, convW0);
        } else {
            const float* W = convWs + (size_t)(l - 1) * HID * HID;
            k_gemm<HID, true><<<ggrid, 256>>>(nullptr, W);
        }
        k_init_agg<<<elemBlocks, TPB>>>(convB + (size_t)l * HID);
        k_scatter<<<scatBlocks, TPB>>>(ei);
        k_bnprep<<<1, HID>>>(bn_g + (size_t)l * HID, bn_b + (size_t)l * HID,
                             bn_m + (size_t)l * HID, bn_v + (size_t)l * HID);
        k_bnrelu<<<elemBlocks, TPB>>>();
    }

    k_zero_pool<<<(N_GRAPHS * HID + TPB - 1) / TPB, TPB>>>();
    k_pool<<<poolBlocks, TPB>>>(batch);
    k_mlp<<<N_GRAPHS, 128>>>(lin1W, lin1b, lin2W, lin2b, out);
}

// round 7
// speedup vs baseline: 2.0306x; 2.0306x over previous
#include <cuda_runtime.h>
#include <cstdint>

#define N_NODES 50000
#define N_EDGES 800000
#define N_GRAPHS 2048
#define IN_DIM 128
#define HID 256
#define N_LAYERS 4
#define BN_EPS 1e-5f

// ---------------- scratch (no allocations allowed) ----------------
__device__ __align__(16) float g_dinv[N_NODES];
__device__ __align__(16) float g_self[N_NODES];
__device__ __align__(16) float g_H[(size_t)N_NODES * HID];   // h = X @ W
__device__ __align__(16) float g_X[(size_t)N_NODES * HID];   // activations
__device__ __align__(16) float g_sc4[N_LAYERS][HID];
__device__ __align__(16) float g_sh4[N_LAYERS][HID];
__device__ int   g_degi[N_NODES];
__device__ int   g_fill[N_NODES];
__device__ int   g_off[N_NODES + 1];
__device__ int   g_csr_src[N_EDGES];
__device__ __align__(16) float g_csr_w[N_EDGES];
__device__ int   g_start[N_GRAPHS + 1];
__device__ int   g_is64;

// ---------------- index dtype sniffing ----------------
// Indices may be int64 or int32 (JAX x64 off demotes). For int64 < 2^31 all
// odd 32-bit words are zero; for int32 they are random node ids.
__global__ void k_sniff(const unsigned* __restrict__ ei_raw) {
    unsigned acc = 0;
    for (int i = 1; i < 128; i += 2) acc |= ei_raw[i];
    g_is64 = (acc == 0) ? 1 : 0;
}

__device__ __forceinline__ int idx_at(const void* base, long long i) {
    if (g_is64) return (int)((const long long*)base)[i];
    return ((const int*)base)[i];
}

// ---------------- setup: degree / norms / CSR / bounds / BN prep -------
__global__ void k_zero_int() {
    int i = blockIdx.x * blockDim.x + threadIdx.x;
    if (i < N_NODES) { g_degi[i] = 0; g_fill[i] = 0; }
}

__global__ void k_degi(const void* __restrict__ ei) {
    int e = blockIdx.x * blockDim.x + threadIdx.x;
    if (e < N_EDGES) atomicAdd(&g_degi[idx_at(ei, (long long)N_EDGES + e)], 1);
}

__global__ void k_norms() {
    int i = blockIdx.x * blockDim.x + threadIdx.x;
    if (i < N_NODES) {
        float d = (float)g_degi[i] + 1.0f;   // self loop
        g_dinv[i] = rsqrtf(d);
        g_self[i] = 1.0f / d;
    }
}

// single-block exclusive scan of g_degi -> g_off (50001 entries)
__global__ __launch_bounds__(1024)
void k_scan() {
    const int C = (N_NODES + 1023) / 1024;   // 49
    __shared__ int ps[1024];
    int t = threadIdx.x;
    int base = t * C;
    int sum = 0;
    for (int c = 0; c < C; c++) {
        int i = base + c;
        if (i < N_NODES) sum += g_degi[i];
    }
    ps[t] = sum;
    __syncthreads();
    for (int off = 1; off < 1024; off <<= 1) {
        int v = (t >= off) ? ps[t - off] : 0;
        __syncthreads();
        ps[t] += v;
        __syncthreads();
    }
    int ex = (t == 0) ? 0 : ps[t - 1];
    for (int c = 0; c < C; c++) {
        int i = base + c;
        if (i < N_NODES) { g_off[i] = ex; ex += g_degi[i]; }
    }
    if (t == 1023) g_off[N_NODES] = ex;
}

__global__ void k_fill(const void* __restrict__ ei) {
    int e = blockIdx.x * blockDim.x + threadIdx.x;
    if (e >= N_EDGES) return;
    int s = idx_at(ei, e);
    int d = idx_at(ei, (long long)N_EDGES + e);
    int pos = g_off[d] + atomicAdd(&g_fill[d], 1);
    g_csr_src[pos] = s;
    g_csr_w[pos] = g_dinv[s] * g_dinv[d];
}

// batch is sorted: find per-graph node ranges
__global__ void k_gbounds(const void* __restrict__ batch) {
    int i = blockIdx.x * blockDim.x + threadIdx.x;
    if (i > N_NODES) return;
    if (i == 0) {
        int b0 = idx_at(batch, 0);
        for (int g = 0; g <= b0; g++) g_start[g] = 0;
    } else if (i == N_NODES) {
        int bl = idx_at(batch, N_NODES - 1);
        for (int g = bl + 1; g <= N_GRAPHS; g++) g_start[g] = N_NODES;
    } else {
        int bp = idx_at(batch, i - 1), bc = idx_at(batch, i);
        for (int g = bp + 1; g <= bc; g++) g_start[g] = i;
    }
}

// fold conv bias into BN shift: out = sc*agg + (sc*(bias-mean) + beta)
__global__ void k_prep(const float* __restrict__ convB,
                       const float* __restrict__ gamma,
                       const float* __restrict__ beta,
                       const float* __restrict__ mean,
                       const float* __restrict__ var) {
    int j = threadIdx.x;   // 256
    for (int l = 0; l < N_LAYERS; l++) {
        int o = l * HID + j;
        float sc = gamma[o] * rsqrtf(var[o] + BN_EPS);
        g_sc4[l][j] = sc;
        g_sh4[l][j] = sc * (convB[o] - mean[o]) + beta[o];
    }
}

// ---------------- GEMM: g_H = A[N,K] @ W[K,256] ----------------
// BM=128, BN=128, BK=8, 256 threads, 8x8 per thread, register prefetch.
template<int K, bool USE_GX>
__global__ __launch_bounds__(256)
void k_gemm(const float* __restrict__ Ain, const float* __restrict__ W) {
    __shared__ float As[8][128];
    __shared__ float Bs[8][128];

    const float* A = USE_GX ? (const float*)g_X : Ain;
    int t = threadIdx.x;
    int tx = t & 15, ty = t >> 4;
    int rowBase = blockIdx.x * 128;
    int colBase = blockIdx.y * 128;

    int ar = t >> 1;            // 0..127 (A row within tile)
    int aq = (t & 1) * 4;       // k sub-offset 0 or 4
    int bk = t >> 5;            // 0..7   (B k-row)
    int bc = (t & 31) * 4;      // 0..124 (B col)

    float acc[8][8] = {};
    float4 aPre, bPre;

    {
        int row = rowBase + ar;
        aPre = (row < N_NODES) ? *(const float4*)(A + (size_t)row * K + aq)
                               : make_float4(0.f, 0.f, 0.f, 0.f);
        bPre = *(const float4*)(W + (size_t)bk * HID + colBase + bc);
    }

    for (int k0 = 0; k0 < K; k0 += 8) {
        As[aq + 0][ar] = aPre.x;
        As[aq + 1][ar] = aPre.y;
        As[aq + 2][ar] = aPre.z;
        As[aq + 3][ar] = aPre.w;
        *(float4*)&Bs[bk][bc] = bPre;
        __syncthreads();

        if (k0 + 8 < K) {
            int row = rowBase + ar;
            aPre = (row < N_NODES)
                 ? *(const float4*)(A + (size_t)row * K + k0 + 8 + aq)
                 : make_float4(0.f, 0.f, 0.f, 0.f);
            bPre = *(const float4*)(W + (size_t)(k0 + 8 + bk) * HID + colBase + bc);
        }

        #pragma unroll
        for (int k = 0; k < 8; k++) {
            float4 a0 = *(const float4*)&As[k][ty * 4];
            float4 a1 = *(const float4*)&As[k][64 + ty * 4];
            float4 b0 = *(const float4*)&Bs[k][tx * 4];
            float4 b1 = *(const float4*)&Bs[k][64 + tx * 4];
            float av[8] = {a0.x, a0.y, a0.z, a0.w, a1.x, a1.y, a1.z, a1.w};
            float bv[8] = {b0.x, b0.y, b0.z, b0.w, b1.x, b1.y, b1.z, b1.w};
            #pragma unroll
            for (int i = 0; i < 8; i++)
                #pragma unroll
                for (int j = 0; j < 8; j++)
                    acc[i][j] += av[i] * bv[j];
        }
        __syncthreads();
    }

    #pragma unroll
    for (int i = 0; i < 8; i++) {
        int row = rowBase + ((i < 4) ? (ty * 4 + i) : (64 + ty * 4 + i - 4));
        if (row < N_NODES) {
            float* p = g_H + (size_t)row * HID + colBase;
            *(float4*)(p + tx * 4)      = make_float4(acc[i][0], acc[i][1], acc[i][2], acc[i][3]);
            *(float4*)(p + 64 + tx * 4) = make_float4(acc[i][4], acc[i][5], acc[i][6], acc[i][7]);
        }
    }
}

// ---------------- fused gather + self + BN + ReLU ----------------
// X[i] = relu( sc * (self[i]*H[i] + sum_e w_e * H[src_e]) + sh )
// 64 threads/node, thread handles a float4 of channels. No atomics.
__global__ __launch_bounds__(256)
void k_agg(int layer) {
    int tid = blockIdx.x * blockDim.x + threadIdx.x;
    int i = tid >> 6;
    if (i >= N_NODES) return;
    int j = (tid & 63) << 2;

    float s = g_self[i];
    float4 h = *(const float4*)(g_H + (size_t)i * HID + j);
    float4 acc = make_float4(h.x * s, h.y * s, h.z * s, h.w * s);

    int k = g_off[i], kend = g_off[i + 1];
    for (; k + 1 < kend; k += 2) {
        int   s0 = g_csr_src[k],     s1 = g_csr_src[k + 1];
        float w0 = g_csr_w[k],       w1 = g_csr_w[k + 1];
        float4 h0 = *(const float4*)(g_H + (size_t)s0 * HID + j);
        float4 h1 = *(const float4*)(g_H + (size_t)s1 * HID + j);
        acc.x += w0 * h0.x + w1 * h1.x;
        acc.y += w0 * h0.y + w1 * h1.y;
        acc.z += w0 * h0.z + w1 * h1.z;
        acc.w += w0 * h0.w + w1 * h1.w;
    }
    if (k < kend) {
        int   s0 = g_csr_src[k];
        float w0 = g_csr_w[k];
        float4 h0 = *(const float4*)(g_H + (size_t)s0 * HID + j);
        acc.x += w0 * h0.x; acc.y += w0 * h0.y;
        acc.z += w0 * h0.z; acc.w += w0 * h0.w;
    }

    float4 sc = *(const float4*)(&g_sc4[layer][j]);
    float4 sh = *(const float4*)(&g_sh4[layer][j]);
    float4 o;
    o.x = fmaxf(acc.x * sc.x + sh.x, 0.f);
    o.y = fmaxf(acc.y * sc.y + sh.y, 0.f);
    o.z = fmaxf(acc.z * sc.z + sh.z, 0.f);
    o.w = fmaxf(acc.w * sc.w + sh.w, 0.f);
    *(float4*)(g_X + (size_t)i * HID + j) = o;
}

// ---------------- fused mean-pool + MLP head: one block per graph ------
__global__ __launch_bounds__(128)
void k_pmlp(const float* __restrict__ lin1W, const float* __restrict__ lin1b,
            const float* __restrict__ lin2W, const float* __restrict__ lin2b,
            float* __restrict__ out) {
    __shared__ float row[HID];
    __shared__ float red4[4];
    int g = blockIdx.x;
    int t = threadIdx.x;   // 128

    int s = g_start[g], e = g_start[g + 1];
    float r0 = 0.f, r1 = 0.f;
    for (int n = s; n < e; n++) {
        r0 += g_X[(size_t)n * HID + t];
        r1 += g_X[(size_t)n * HID + t + 128];
    }
    float inv = 1.0f / fmaxf((float)(e - s), 1.0f);
    row[t] = r0 * inv;
    row[t + 128] = r1 * inv;
    __syncthreads();

    float acc = lin1b[t];
    #pragma unroll 8
    for (int k = 0; k < HID; k++)
        acc += row[k] * lin1W[(size_t)k * 128 + t];
    float h = fmaxf(acc, 0.f);

    float p = h * lin2W[t];
    #pragma unroll
    for (int o = 16; o > 0; o >>= 1)
        p += __shfl_down_sync(0xffffffffu, p, o);
    if ((t & 31) == 0) red4[t >> 5] = p;
    __syncthreads();
    if (t == 0) out[g] = red4[0] + red4[1] + red4[2] + red4[3] + lin2b[0];
}

// ---------------- launch ----------------
extern "C" void kernel_launch(void* const* d_in, const int* in_sizes, int n_in,
                              void* d_out, int out_size) {
    const float* x      = (const float*)d_in[0];
    const void*  ei     = d_in[1];
    const void*  batch  = d_in[2];
    const float* convW0 = (const float*)d_in[3];
    const float* convWs = (const float*)d_in[4];
    const float* convB  = (const float*)d_in[5];
    const float* bn_g   = (const float*)d_in[6];
    const float* bn_b   = (const float*)d_in[7];
    const float* bn_m   = (const float*)d_in[8];
    const float* bn_v   = (const float*)d_in[9];
    const float* lin1W  = (const float*)d_in[10];
    const float* lin1b  = (const float*)d_in[11];
    const float* lin2W  = (const float*)d_in[12];
    const float* lin2b  = (const float*)d_in[13];
    float* out = (float*)d_out;

    const int TPB = 256;
    int nodeBlocks = (N_NODES + TPB - 1) / TPB;
    int nb1Blocks  = (N_NODES + 1 + TPB - 1) / TPB;
    int edgeBlocks = (N_EDGES + TPB - 1) / TPB;
    int aggBlocks  = (N_NODES * 64 + TPB - 1) / TPB;   // 12500

    k_sniff<<<1, 1>>>((const unsigned*)ei);
    k_zero_int<<<nodeBlocks, TPB>>>();
    k_degi<<<edgeBlocks, TPB>>>(ei);
    k_norms<<<nodeBlocks, TPB>>>();
    k_scan<<<1, 1024>>>();
    k_fill<<<edgeBlocks, TPB>>>(ei);
    k_gbounds<<<nb1Blocks, TPB>>>(batch);
    k_prep<<<1, HID>>>(convB, bn_g, bn_b, bn_m, bn_v);

    dim3 ggrid((N_NODES + 127) / 128, HID / 128);
    for (int l = 0; l < N_LAYERS; l++) {
        if (l == 0) {
            k_gemm<IN_DIM, false><<<ggrid, 256>>>(x, convW0);
        } else {
            const float* W = convWs + (size_t)(l - 1) * HID * HID;
            k_gemm<HID, true><<<ggrid, 256>>>(nullptr, W);
        }
        k_agg<<<aggBlocks, TPB>>>(l);
    }

    k_pmlp<<<N_GRAPHS, 128>>>(lin1W, lin1b, lin2W, lin2b, out);
}